// round 2
// baseline (speedup 1.0000x reference)
#include <cuda_runtime.h>
#include <cuda_bf16.h>
#include <cstdint>

// Problem constants
#define B_      32
#define C_      3
#define H_      257
#define W_      257
#define MASK_   17
#define STRIDE_ 4
#define NW_     61                 // windows per axis
#define WSZ_    289                // 17*17
#define PLANE_  (257*257)          // 66049
#define NWIN_   (B_*C_*NW_*NW_)    // 357216 windows total
#define SW_ELEMS  ((long long)NWIN_ * WSZ_)        // 103,235,424
#define S_ELEMS   ((long long)B_ * 12 * NW_ * NW_) // 1,428,864
#define S_OFF     SW_ELEMS
#define Q_OFF     (SW_ELEMS + S_ELEMS)             // 104,664,288 (divisible by 4)

// One warp per 17x17 window. Output stream vectorized to float4 (STG.128):
// window base alignment class = wid mod 4, so each warp uses phase offset
// a = (-wid)&3 : [a head scalars][71..72 aligned float4 groups][<=3 tail scalars].
__global__ __launch_bounds__(256) void leafnet_fused_kernel(
    const float* __restrict__ x, float* __restrict__ out)
{
    const int gtid = blockIdx.x * blockDim.x + threadIdx.x;
    const int wid  = gtid >> 5;
    const int lane = gtid & 31;
    if (wid >= NWIN_) return;

    // wid = ((b*3 + c)*61 + i)*61 + j
    const int j  = wid % NW_;
    const int t  = wid / NW_;
    const int i  = t % NW_;
    const int bc = t / NW_;   // b*3 + c

    const float* xb  = x + (size_t)bc * PLANE_ + (size_t)(i * STRIDE_) * W_ + j * STRIDE_;
    float* swp = out + (size_t)wid * WSZ_;
    float* qp  = out + (size_t)Q_OFF + (size_t)wid * WSZ_;

    const int a         = (-wid) & 3;         // head count to reach 16B alignment
    const int ngroups   = (WSZ_ - a) >> 2;    // 71 or 72 float4 groups
    const int tailstart = a + (ngroups << 2);
    const int tail      = WSZ_ - tailstart;   // 0..3

    float sum   = 0.0f;
    float sumsq = 0.0f;
    float vmin  =  1e30f;
    float vmax  = -1e30f;

    auto doScalar = [&](int e) {
        const int u = (e * 241) >> 12;        // e / 17 (exact for 0<=e<=288)
        const int v = e - u * 17;
        const float val = __ldg(xb + u * W_ + v);
        __stcs(swp + e, val);
        __stcs(qp  + e, floorf(val * 64.0f)); // digitize(linspace(0,1,65)) - 1
        sum   += val;
        sumsq  = fmaf(val, val, sumsq);
        vmin   = fminf(vmin, val);
        vmax   = fmaxf(vmax, val);
    };

    auto doGroup = [&](int e0) {              // e0 16B-aligned within out
        float w[4], q[4];
        #pragma unroll
        for (int tt = 0; tt < 4; tt++) {
            const int e = e0 + tt;
            const int u = (e * 241) >> 12;
            const int v = e - u * 17;
            w[tt] = __ldg(xb + u * W_ + v);
        }
        #pragma unroll
        for (int tt = 0; tt < 4; tt++) {
            q[tt]  = floorf(w[tt] * 64.0f);
            sum   += w[tt];
            sumsq  = fmaf(w[tt], w[tt], sumsq);
            vmin   = fminf(vmin, w[tt]);
            vmax   = fmaxf(vmax, w[tt]);
        }
        __stcs(reinterpret_cast<float4*>(swp + e0), make_float4(w[0], w[1], w[2], w[3]));
        __stcs(reinterpret_cast<float4*>(qp  + e0), make_float4(q[0], q[1], q[2], q[3]));
    };

    if (lane < a) doScalar(lane);
    doGroup(a + 4 * lane);                    // lane      < 71 <= ngroups : always
    doGroup(a + 4 * (lane + 32));             // lane + 32 < 64 < 71      : always
    if (lane + 64 < ngroups) doGroup(a + 4 * (lane + 64));  // 7-8 lanes
    if (lane < tail) doScalar(tailstart + lane);

    // Warp reduction (butterfly)
    #pragma unroll
    for (int o = 16; o > 0; o >>= 1) {
        sum   += __shfl_xor_sync(0xFFFFFFFFu, sum,   o);
        sumsq += __shfl_xor_sync(0xFFFFFFFFu, sumsq, o);
        vmin   = fminf(vmin, __shfl_xor_sync(0xFFFFFFFFu, vmin, o));
        vmax   = fmaxf(vmax, __shfl_xor_sync(0xFFFFFFFFu, vmax, o));
    }

    if (lane == 0) {
        const float inv  = 1.0f / 289.0f;
        const float mean = sum * inv;
        const float var  = fmaxf(sumsq * inv - mean * mean, 0.0f);
        const float stdv = sqrtf(var);

        const int b = bc / 3;
        const int c = bc - b * 3;
        const int pos = i * NW_ + j;
        float* sp = out + (size_t)S_OFF + (size_t)b * 12 * (NW_ * NW_);
        // channel layout: [ (max-0.5)*4 | std*4 | (max-mean)*4 | (mean-min)*4 ] x C
        sp[(0 * 3 + c) * (NW_ * NW_) + pos] = (vmax - 0.5f) * 4.0f;
        sp[(1 * 3 + c) * (NW_ * NW_) + pos] = stdv * 4.0f;
        sp[(2 * 3 + c) * (NW_ * NW_) + pos] = (vmax - mean) * 4.0f;
        sp[(3 * 3 + c) * (NW_ * NW_) + pos] = (mean - vmin) * 4.0f;
    }
}

extern "C" void kernel_launch(void* const* d_in, const int* in_sizes, int n_in,
                              void* d_out, int out_size)
{
    const float* x = (const float*)d_in[0];   // (32,3,257,257) float32
    // d_in[1] = bins (65 floats) — uniform linspace(0,1,65); digitize-1 == floor(v*64)
    float* out = (float*)d_out;

    const int threads = 256;                          // 8 warps = 8 windows / block
    const int blocks  = (NWIN_ * 32 + threads - 1) / threads;  // 44652
    leafnet_fused_kernel<<<blocks, threads>>>(x, out);
}

// round 3
// speedup vs baseline: 1.2400x; 1.2400x over previous
#include <cuda_runtime.h>
#include <cuda_bf16.h>
#include <cstdint>

// Problem constants
#define B_      32
#define C_      3
#define H_      257
#define W_      257
#define MASK_   17
#define STRIDE_ 4
#define NW_     61                 // windows per axis
#define WSZ_    289                // 17*17
#define PLANE_  (257*257)          // 66049
#define NWIN_   (B_*C_*NW_*NW_)    // 357216 windows total
#define SW_ELEMS  ((long long)NWIN_ * WSZ_)        // 103,235,424
#define S_ELEMS   ((long long)B_ * 12 * NW_ * NW_) // 1,428,864
#define S_OFF     SW_ELEMS
#define Q_OFF     (SW_ELEMS + S_ELEMS)             // 104,664,288 (divisible by 4)

#define JT_       8                 // windows per block (along j)
#define NJT_      8                 // ceil(61/8) j-tiles
#define TILE_COLS 45                // (JT_-1)*4 + 17
#define TILE_PAD  48                // padded row stride in smem
#define TILE_ROWS 17

// Block = 8 adjacent windows along j (same bc, i). x tile (17 x 45) staged in
// smem with one coalesced pass; each warp then processes one window from smem
// and writes sw/q with phased float4 stores.
__global__ __launch_bounds__(256) void leafnet_fused_kernel(
    const float* __restrict__ x, float* __restrict__ out)
{
    __shared__ float tile[TILE_ROWS * TILE_PAD];

    // blockIdx.x -> (bc, i, jt)
    const int jt   = blockIdx.x & 7;          // NJT_ = 8
    const int rest = blockIdx.x >> 3;
    const int i    = rest % NW_;
    const int bc   = rest / NW_;               // b*3 + c
    const int j0   = jt * JT_;

    // ---- Cooperative coalesced tile load: rows [i*4, i*4+17), cols [j0*4, j0*4+45)
    {
        const float* xrow = x + (size_t)bc * PLANE_ + (size_t)(i * STRIDE_) * W_;
        const int cbase = j0 * STRIDE_;
        #pragma unroll
        for (int p = 0; p < 3; p++) {
            const int idx = threadIdx.x + p * 256;     // 0..767; 765 valid
            if (idx < TILE_ROWS * TILE_COLS) {
                const int u = idx / TILE_COLS;
                const int c = idx - u * TILE_COLS;
                const int gc = cbase + c;
                tile[u * TILE_PAD + c] = (gc < W_) ? __ldg(xrow + u * W_ + gc) : 0.0f;
            }
        }
    }
    __syncthreads();

    const int w    = threadIdx.x >> 5;          // window slot in tile (0..7)
    const int lane = threadIdx.x & 31;
    const int j    = j0 + w;
    if (j >= NW_) return;                       // only last jt loses warps 5..7

    const int wid = (bc * NW_ + i) * NW_ + j;
    const float* wsm = tile + w * STRIDE_;      // + u*TILE_PAD + v
    float* swp = out + (size_t)wid * WSZ_;
    float* qp  = out + (size_t)Q_OFF + (size_t)wid * WSZ_;

    const int a         = (-wid) & 3;           // head count to reach 16B alignment
    const int ngroups   = (WSZ_ - a) >> 2;      // 71 or 72 float4 groups
    const int tailstart = a + (ngroups << 2);
    const int tail      = WSZ_ - tailstart;     // 0..3

    float sum   = 0.0f;
    float sumsq = 0.0f;
    float vmin  =  1e30f;
    float vmax  = -1e30f;

    auto doScalar = [&](int e) {
        const int u = (e * 241) >> 12;          // e / 17 (exact for 0<=e<=288)
        const int v = e - u * 17;
        const float val = wsm[u * TILE_PAD + v];
        __stcs(swp + e, val);
        __stcs(qp  + e, floorf(val * 64.0f));   // digitize(linspace(0,1,65)) - 1
        sum   += val;
        sumsq  = fmaf(val, val, sumsq);
        vmin   = fminf(vmin, val);
        vmax   = fmaxf(vmax, val);
    };

    auto doGroup = [&](int e0) {                // e0 16B-aligned within out
        float wv[4], q[4];
        #pragma unroll
        for (int tt = 0; tt < 4; tt++) {
            const int e = e0 + tt;
            const int u = (e * 241) >> 12;
            const int v = e - u * 17;
            wv[tt] = wsm[u * TILE_PAD + v];
        }
        #pragma unroll
        for (int tt = 0; tt < 4; tt++) {
            q[tt]  = floorf(wv[tt] * 64.0f);
            sum   += wv[tt];
            sumsq  = fmaf(wv[tt], wv[tt], sumsq);
            vmin   = fminf(vmin, wv[tt]);
            vmax   = fmaxf(vmax, wv[tt]);
        }
        __stcs(reinterpret_cast<float4*>(swp + e0), make_float4(wv[0], wv[1], wv[2], wv[3]));
        __stcs(reinterpret_cast<float4*>(qp  + e0), make_float4(q[0], q[1], q[2], q[3]));
    };

    if (lane < a) doScalar(lane);
    doGroup(a + 4 * lane);                      // lane      < 71 <= ngroups : always
    doGroup(a + 4 * (lane + 32));               // lane + 32 < 64 < 71      : always
    if (lane + 64 < ngroups) doGroup(a + 4 * (lane + 64));   // 7-8 lanes
    if (lane < tail) doScalar(tailstart + lane);

    // Warp reduction (butterfly)
    #pragma unroll
    for (int o = 16; o > 0; o >>= 1) {
        sum   += __shfl_xor_sync(0xFFFFFFFFu, sum,   o);
        sumsq += __shfl_xor_sync(0xFFFFFFFFu, sumsq, o);
        vmin   = fminf(vmin, __shfl_xor_sync(0xFFFFFFFFu, vmin, o));
        vmax   = fmaxf(vmax, __shfl_xor_sync(0xFFFFFFFFu, vmax, o));
    }

    if (lane == 0) {
        const float inv  = 1.0f / 289.0f;
        const float mean = sum * inv;
        const float var  = fmaxf(sumsq * inv - mean * mean, 0.0f);
        const float stdv = sqrtf(var);

        const int b = bc / 3;
        const int c = bc - b * 3;
        const int pos = i * NW_ + j;
        float* sp = out + (size_t)S_OFF + (size_t)b * 12 * (NW_ * NW_);
        // channel layout: [ (max-0.5)*4 | std*4 | (max-mean)*4 | (mean-min)*4 ] x C
        sp[(0 * 3 + c) * (NW_ * NW_) + pos] = (vmax - 0.5f) * 4.0f;
        sp[(1 * 3 + c) * (NW_ * NW_) + pos] = stdv * 4.0f;
        sp[(2 * 3 + c) * (NW_ * NW_) + pos] = (vmax - mean) * 4.0f;
        sp[(3 * 3 + c) * (NW_ * NW_) + pos] = (mean - vmin) * 4.0f;
    }
}

extern "C" void kernel_launch(void* const* d_in, const int* in_sizes, int n_in,
                              void* d_out, int out_size)
{
    const float* x = (const float*)d_in[0];   // (32,3,257,257) float32
    // d_in[1] = bins (65 floats) — uniform linspace(0,1,65); digitize-1 == floor(v*64)
    float* out = (float*)d_out;

    const int threads = 256;                  // 8 warps = 8 windows / block
    const int blocks  = (B_ * C_) * NW_ * NJT_;  // 96 * 61 * 8 = 46848
    leafnet_fused_kernel<<<blocks, threads>>>(x, out);
}